// round 9
// baseline (speedup 1.0000x reference)
#include <cuda_runtime.h>
#include <math.h>

#define N_COMBOS   64
#define N_STRUCTS  512
#define HID        1024
#define BATCH      2048
#define NITERS     60
#define POW_ITERS  30

#define MAX_NNZ_G  32768
#define MAX_LR     96
#define COLCAP     8192
#define RPB        4        // batch rows per PDHG block (2 warps per row)

// ---------------- device scratch ----------------
__device__ float g_A1[BATCH * HID];
__device__ float g_A2[BATCH * HID];
__device__ float g_Z [BATCH * N_STRUCTS];
__device__ float g_tau;

__device__ int            g_row_ptr[N_COMBOS + 1];
__device__ unsigned short g_row_idx[MAX_NNZ_G];
__device__ int            g_col_ptr[N_STRUCTS + 1];
__device__ unsigned char  g_col_idx[MAX_NNZ_G];

__device__ unsigned int   g_ellr[MAX_LR * 32];   // [p][lane]: idx(row=lane) | idx(row=lane+32)<<16 ; sentinel 512
__device__ int            g_len_ellr;
__device__ unsigned short g_cp4[N_STRUCTS + 1];  // padded (mult of 4) CSC offsets
__device__ unsigned char  g_ci4[COLCAP];         // padded CSC col indices; sentinel 64

// ---------------- prep (unchanged from R7) ----------------
__global__ __launch_bounds__(512) void prep_kernel(const float* __restrict__ S) {
    __shared__ int cnt[N_STRUCTS];
    int tid = threadIdx.x;

    if (tid < N_COMBOS) {
        int c = 0;
        for (int j = 0; j < N_STRUCTS; j++) if (S[tid * N_STRUCTS + j] != 0.f) c++;
        cnt[tid] = c;
    }
    __syncthreads();
    if (tid == 0) {
        int acc = 0;
        for (int i = 0; i < N_COMBOS; i++) { g_row_ptr[i] = acc; acc += cnt[i]; }
        g_row_ptr[N_COMBOS] = acc;
    }
    __syncthreads();
    if (tid < N_COMBOS) {
        int p = g_row_ptr[tid];
        for (int j = 0; j < N_STRUCTS; j++)
            if (S[tid * N_STRUCTS + j] != 0.f) g_row_idx[p++] = (unsigned short)j;
    }
    __syncthreads();

    {
        int c = 0;
        for (int i = 0; i < N_COMBOS; i++) if (S[i * N_STRUCTS + tid] != 0.f) c++;
        cnt[tid] = c;
    }
    __syncthreads();
    if (tid == 0) {
        int acc = 0;
        for (int j = 0; j < N_STRUCTS; j++) { g_col_ptr[j] = acc; acc += cnt[j]; }
        g_col_ptr[N_STRUCTS] = acc;
    }
    __syncthreads();
    {
        int p = g_col_ptr[tid];
        for (int i = 0; i < N_COMBOS; i++)
            if (S[i * N_STRUCTS + tid] != 0.f) g_col_idx[p++] = (unsigned char)i;
    }
    __syncthreads();

    if (tid < 32) {
        int ra = g_row_ptr[tid],      la = g_row_ptr[tid + 1]  - ra;
        int rb = g_row_ptr[tid + 32], lb = g_row_ptr[tid + 33] - rb;
        int L = la > lb ? la : lb;
        if (L > MAX_LR) L = MAX_LR;
        for (int p = 0; p < MAX_LR; p++) {
            unsigned a = (p < la) ? g_row_idx[ra + p] : 512u;
            unsigned b = (p < lb) ? g_row_idx[rb + p] : 512u;
            g_ellr[p * 32 + tid] = a | (b << 16);
        }
        #pragma unroll
        for (int o = 16; o; o >>= 1) { int v = __shfl_xor_sync(0xffffffffu, L, o); L = v > L ? v : L; }
        if (tid == 0) g_len_ellr = L;
    }
    if (tid == 0) {
        int acc = 0;
        for (int j = 0; j < N_STRUCTS; j++) {
            g_cp4[j] = (unsigned short)acc;
            int l = g_col_ptr[j + 1] - g_col_ptr[j];
            acc += (l + 3) & ~3;
        }
        g_cp4[N_STRUCTS] = (unsigned short)acc;
    }
    __syncthreads();
    {
        int j = tid;
        int o = g_cp4[j];
        int base = g_col_ptr[j];
        int l = g_col_ptr[j + 1] - base;
        int pl = (l + 3) & ~3;
        for (int p = 0; p < pl && (o + p) < COLCAP; p++)
            g_ci4[o + p] = (p < l) ? g_col_idx[base + p] : (unsigned char)64;
    }
}

// ---------------- power iteration (unchanged) ----------------
__global__ __launch_bounds__(512) void power_kernel() {
    __shared__ float v[N_STRUCTS];
    __shared__ float t[N_COMBOS];
    __shared__ float red[16];
    int tid = threadIdx.x;

    v[tid] = 1.0f / sqrtf((float)N_STRUCTS);
    __syncthreads();

    for (int it = 0; it < POW_ITERS; it++) {
        if (tid < N_COMBOS) {
            float s = 0.f;
            int pe = g_row_ptr[tid + 1];
            for (int p = g_row_ptr[tid]; p < pe; p++) s += v[g_row_idx[p]];
            t[tid] = s;
        }
        __syncthreads();
        float w;
        {
            float s = 0.f;
            int pe = g_col_ptr[tid + 1];
            for (int p = g_col_ptr[tid]; p < pe; p++) s += t[g_col_idx[p]];
            w = s + v[tid];
        }
        float sq = w * w;
        #pragma unroll
        for (int o = 16; o; o >>= 1) sq += __shfl_xor_sync(0xffffffffu, sq, o);
        if ((tid & 31) == 0) red[tid >> 5] = sq;
        __syncthreads();
        float tot = 0.f;
        #pragma unroll
        for (int k = 0; k < 16; k++) tot += red[k];
        v[tid] = w / sqrtf(tot);
        __syncthreads();
    }

    if (tid < N_COMBOS) {
        float s = 0.f;
        int pe = g_row_ptr[tid + 1];
        for (int p = g_row_ptr[tid]; p < pe; p++) s += v[g_row_idx[p]];
        t[tid] = s;
    }
    __syncthreads();
    float w;
    {
        float s = 0.f;
        int pe = g_col_ptr[tid + 1];
        for (int p = g_col_ptr[tid]; p < pe; p++) s += t[g_col_idx[p]];
        w = s + v[tid];
    }
    float dq = v[tid] * w;
    #pragma unroll
    for (int o = 16; o; o >>= 1) dq += __shfl_xor_sync(0xffffffffu, dq, o);
    if ((tid & 31) == 0) red[tid >> 5] = dq;
    __syncthreads();
    if (tid == 0) {
        float tot = 0.f;
        #pragma unroll
        for (int k = 0; k < 16; k++) tot += red[k];
        g_tau = 0.9f / sqrtf(tot);
    }
}

// ---------------- GEMM + bias + relu (64x64x32, 128 threads, 8x4) ----------------
__global__ __launch_bounds__(128) void gemm_bias_relu(
    const float* __restrict__ A, const float* __restrict__ B,
    const float* __restrict__ bias, float* __restrict__ C,
    int M, int N, int K)
{
    const int BK = 32;
    __shared__ __align__(16) float As[BK][64];
    __shared__ __align__(16) float Bs[BK][64];

    const int tid = threadIdx.x;
    const int bm = blockIdx.y * 64;
    const int bn = blockIdx.x * 64;

    const int a_r = tid >> 1, a_c = (tid & 1) * 16;   // 16 consecutive k's per thread
    const int b_r = tid >> 2, b_c = (tid & 3) * 16;   // 16 consecutive n's per thread
    const int tx = tid & 15, ty = tid >> 4;

    float acc[8][4];
    #pragma unroll
    for (int i = 0; i < 8; i++)
        #pragma unroll
        for (int j = 0; j < 4; j++) acc[i][j] = 0.f;

    for (int k0 = 0; k0 < K; k0 += BK) {
        #pragma unroll
        for (int v = 0; v < 4; v++) {
            float4 av = *(const float4*)&A[(size_t)(bm + a_r) * K + k0 + a_c + v * 4];
            As[a_c + v * 4 + 0][a_r] = av.x;
            As[a_c + v * 4 + 1][a_r] = av.y;
            As[a_c + v * 4 + 2][a_r] = av.z;
            As[a_c + v * 4 + 3][a_r] = av.w;
        }
        #pragma unroll
        for (int v = 0; v < 4; v++) {
            float4 bv = *(const float4*)&B[(size_t)(k0 + b_r) * N + bn + b_c + v * 4];
            *(float4*)&Bs[b_r][b_c + v * 4] = bv;
        }
        __syncthreads();

        #pragma unroll
        for (int k = 0; k < BK; k++) {
            float4 a0 = *(const float4*)&As[k][ty * 8];
            float4 a1 = *(const float4*)&As[k][ty * 8 + 4];
            float4 b0 = *(const float4*)&Bs[k][tx * 4];
            float a[8] = {a0.x, a0.y, a0.z, a0.w, a1.x, a1.y, a1.z, a1.w};
            float bb[4] = {b0.x, b0.y, b0.z, b0.w};
            #pragma unroll
            for (int i = 0; i < 8; i++)
                #pragma unroll
                for (int j = 0; j < 4; j++)
                    acc[i][j] = fmaf(a[i], bb[j], acc[i][j]);
        }
        __syncthreads();
    }

    #pragma unroll
    for (int j = 0; j < 4; j++) {
        float bb = bias[bn + tx * 4 + j];
        #pragma unroll
        for (int i = 0; i < 8; i++) {
            float r = acc[i][j] + bb;
            C[(size_t)(bm + ty * 8 + i) * N + bn + tx * 4 + j] = r > 0.f ? r : 0.f;
        }
    }
}

// ---------------- PDHG: 2 warps per batch row, 4 rows per block ----------------
__global__ __launch_bounds__(256, 3) void pdhg_split_kernel(
    const float* __restrict__ Zg, const float* __restrict__ Xg,
    float* __restrict__ out)
{
    constexpr int XB = 516;
    __shared__ unsigned int   s_ellr[MAX_LR * 32];     // 12 KB
    __shared__ unsigned short s_cp4[N_STRUCTS + 2];    // 1 KB
    __shared__ unsigned char  s_ci4[COLCAP];           // 8 KB
    __shared__ float          s_xbar[RPB][XB];         // 8.25 KB
    __shared__ float          s_y1[RPB][68];           // 1.1 KB
    __shared__ float          s_pb[RPB][2][32];        // 1 KB (warp-B partials)
    __shared__ float          s_ns[8];                 // per-warp sumsq

    const int tid = threadIdx.x;
    const int w   = tid >> 5;
    const int l   = tid & 31;
    const int r   = w >> 1;          // local batch row 0..3
    const int h   = w & 1;           // half: 0 = cols 0..255, 1 = cols 256..511
    const int row = blockIdx.x * RPB + r;
    const float tau = g_tau;
    const float sigma = tau;
    const int LEN  = g_len_ellr;
    const int LENH = (LEN + 1) >> 1;

    for (int p = tid; p < LEN * 32; p += 256) s_ellr[p] = g_ellr[p];
    for (int p = tid; p <= N_STRUCTS; p += 256) s_cp4[p] = g_cp4[p];
    {
        int tot = (g_cp4[N_STRUCTS] + 3) & ~3;
        for (int p = tid * 4; p < tot; p += 1024)
            *(unsigned int*)&s_ci4[p] = *(const unsigned int*)&g_ci4[p];
    }

    float* sx  = s_xbar[r];
    float* sy1 = s_y1[r];

    const float B0 = Xg[row * N_COMBOS + l];
    const float B1 = Xg[row * N_COMBOS + l + 32];
    float yy0 = 0.f, yy1 = 0.f;      // live only in warp A (h==0)

    float Zr[8], xr[8], y2[8], xb[8], dd[8];
    #pragma unroll
    for (int qq = 0; qq < 8; qq++) {
        int j = (h * 8 + qq) * 32 + l;
        Zr[qq] = Zg[(size_t)row * N_STRUCTS + j];
        xr[qq] = 0.f; y2[qq] = 0.f; xb[qq] = 0.f;
        sx[j] = 0.f;
    }
    if (h == 0) {
        if (l < XB - 512) sx[512 + l] = 0.f;       // xbar sentinel
        if (l < 4) sy1[64 + l] = 0.f;              // y1 sentinel
        sy1[l] = 0.f; sy1[l + 32] = 0.f;
    }
    __syncthreads();

    for (int it = 0; it < NITERS; it++) {
        // ---- phase 1: ELL partial row gather (each warp does half the depth) ----
        float s0a = 0.f, s1a = 0.f, s0b = 0.f, s1b = 0.f;
        int p = h ? LENH : 0;
        const int pend = h ? LEN : LENH;
        for (; p + 2 <= pend; p += 2) {
            unsigned ua = s_ellr[p * 32 + l];
            unsigned ub = s_ellr[(p + 1) * 32 + l];
            float va0 = sx[ua & 0xffffu];
            float va1 = sx[ua >> 16];
            float vb0 = sx[ub & 0xffffu];
            float vb1 = sx[ub >> 16];
            s0a += va0; s1a += va1;
            s0b += vb0; s1b += vb1;
        }
        if (p < pend) {
            unsigned ua = s_ellr[p * 32 + l];
            s0a += sx[ua & 0xffffu];
            s1a += sx[ua >> 16];
        }
        float s0 = s0a + s0b, s1 = s1a + s1b;
        if (h == 1) { s_pb[r][0][l] = s0; s_pb[r][1][l] = s1; }

        // ---- y2 update (local registers) ----
        #pragma unroll
        for (int qq = 0; qq < 8; qq++)
            y2[qq] = fmaxf(fmaf(-sigma, xb[qq], y2[qq]), 0.f);
        __syncthreads();

        // ---- phase 2: warp A combines partials, updates y1 ----
        if (h == 0) {
            float t0 = s0 + s_pb[r][0][l];
            float t1 = s1 + s_pb[r][1][l];
            yy0 = fmaxf(fmaf(sigma, t0 - B0, yy0), 0.f);
            yy1 = fmaxf(fmaf(sigma, t1 - B1, yy1), 0.f);
            sy1[l] = yy0;
            sy1[l + 32] = yy1;
        }
        __syncthreads();

        // ---- phase 3: CSC gather for own 8 columns ----
        float sumsq = 0.f;
        #pragma unroll
        for (int qq = 0; qq < 8; qq++) {
            int j = (h * 8 + qq) * 32 + l;
            int o = s_cp4[j], e = s_cp4[j + 1];
            float g = 0.f;
            for (int pp = o; pp < e; pp += 4) {
                unsigned w4 = *(const unsigned int*)&s_ci4[pp];
                g += sy1[w4 & 255u] + sy1[(w4 >> 8) & 255u]
                   + sy1[(w4 >> 16) & 255u] + sy1[w4 >> 24];
            }
            g -= y2[qq];
            float v = fmaf(-tau, g, xr[qq]);
            float d = v + tau - Zr[qq];
            dd[qq] = d;
            sumsq = fmaf(d, d, sumsq);
        }
        #pragma unroll
        for (int o = 16; o; o >>= 1) sumsq += __shfl_xor_sync(0xffffffffu, sumsq, o);
        if (l == 0) s_ns[w] = sumsq;
        __syncthreads();

        // ---- phase 4: scale + prox + xbar write ----
        float tot = s_ns[2 * r] + s_ns[2 * r + 1];
        float scale = fmaxf(1.f - tau / fmaxf(sqrtf(tot), 1e-12f), 0.f);
        #pragma unroll
        for (int qq = 0; qq < 8; qq++) {
            int j = (h * 8 + qq) * 32 + l;
            float xn  = fmaf(scale, dd[qq], Zr[qq]);
            float xbv = 2.f * xn - xr[qq];
            xr[qq] = xn;
            xb[qq] = xbv;
            sx[j] = xbv;
        }
        __syncthreads();
    }

    #pragma unroll
    for (int qq = 0; qq < 8; qq++)
        out[(size_t)row * N_STRUCTS + (h * 8 + qq) * 32 + l] = xr[qq];
}

// ---------------- launch ----------------
extern "C" void kernel_launch(void* const* d_in, const int* in_sizes, int n_in,
                              void* d_out, int out_size) {
    const float* X  = (const float*)d_in[0];
    const float* W1 = (const float*)d_in[1];
    const float* b1 = (const float*)d_in[2];
    const float* W2 = (const float*)d_in[3];
    const float* b2 = (const float*)d_in[4];
    const float* W3 = (const float*)d_in[5];
    const float* b3 = (const float*)d_in[6];
    const float* S  = (const float*)d_in[7];
    float* out = (float*)d_out;

    float *A1, *A2, *Z;
    cudaGetSymbolAddress((void**)&A1, g_A1);
    cudaGetSymbolAddress((void**)&A2, g_A2);
    cudaGetSymbolAddress((void**)&Z,  g_Z);

    prep_kernel<<<1, 512>>>(S);
    power_kernel<<<1, 512>>>();

    gemm_bias_relu<<<dim3(HID / 64, BATCH / 64), 128>>>(X, W1, b1, A1, BATCH, HID, N_COMBOS);
    gemm_bias_relu<<<dim3(HID / 64, BATCH / 64), 128>>>(A1, W2, b2, A2, BATCH, HID, HID);
    gemm_bias_relu<<<dim3(N_STRUCTS / 64, BATCH / 64), 128>>>(A2, W3, b3, Z, BATCH, N_STRUCTS, HID);

    pdhg_split_kernel<<<BATCH / RPB, 256>>>(Z, X, out);
}